// round 8
// baseline (speedup 1.0000x reference)
#include <cuda_runtime.h>
#include <cuda_bf16.h>
#include <math.h>
#include <stdint.h>

#define BATCH 4
#define CH    384
#define IMG   128
#define HWN   (IMG*IMG)      // 16384
#define NH    8
#define HD    48
#define NBH   (BATCH*NH)     // 32
#define GRAM_CHUNKS 32
#define NCHUNK (HWN/GRAM_CHUNKS)
#define KTOT  384

// ---------------- scratch (device globals; no allocation) ----------------
__device__ __align__(16) float g_pre  [3ull*BATCH*CH*HWN];
__device__ __align__(16) float g_post [3ull*BATCH*CH*HWN];
__device__ __align__(16) float g_snp  [2*BATCH*CH*16];
__device__ __align__(16) float g_sqn  [2*BATCH*CH];
__device__ __align__(16) float g_gpart[(size_t)GRAM_CHUNKS*NBH*HD*HD];
__device__ __align__(16) float g_gram [NBH*HD*HD];
// bf16 split operands
__device__ __align__(16) unsigned short g_wh  [(size_t)1536*KTOT];
__device__ __align__(16) unsigned short g_wl  [(size_t)1536*KTOT];
__device__ __align__(16) unsigned short g_inth[(size_t)2*BATCH*HWN*CH];  // [inp][b][p][c]
__device__ __align__(16) unsigned short g_intl[(size_t)2*BATCH*HWN*CH];
__device__ __align__(16) unsigned short g_avh [(size_t)BATCH*HWN*CH];    // [b][p][c]
__device__ __align__(16) unsigned short g_avl [(size_t)BATCH*HWN*CH];

// ---------------- PTX helpers (sm_80-level only) ----------------
__device__ __forceinline__ uint32_t smem_u32(const void* p) {
    uint32_t a;
    asm("{ .reg .u64 t; cvta.to.shared.u64 t, %1; cvt.u32.u64 %0, t; }" : "=r"(a) : "l"(p));
    return a;
}
__device__ __forceinline__ void cpa16(uint32_t saddr, const void* gptr) {
    asm volatile("cp.async.cg.shared.global [%0], [%1], 16;" :: "r"(saddr), "l"(gptr));
}
__device__ __forceinline__ void ldm_x4(uint32_t* r, uint32_t addr) {
    asm volatile("ldmatrix.sync.aligned.m8n8.x4.shared.b16 {%0,%1,%2,%3}, [%4];"
        : "=r"(r[0]), "=r"(r[1]), "=r"(r[2]), "=r"(r[3]) : "r"(addr));
}
__device__ __forceinline__ void ldm_x2(uint32_t* r, uint32_t addr) {
    asm volatile("ldmatrix.sync.aligned.m8n8.x2.shared.b16 {%0,%1}, [%2];"
        : "=r"(r[0]), "=r"(r[1]) : "r"(addr));
}
__device__ __forceinline__ void mma_bf16(float* c, const uint32_t* a, const uint32_t* b) {
    asm volatile("mma.sync.aligned.m16n8k16.row.col.f32.bf16.bf16.f32 "
        "{%0,%1,%2,%3}, {%4,%5,%6,%7}, {%8,%9}, {%0,%1,%2,%3};"
        : "+f"(c[0]), "+f"(c[1]), "+f"(c[2]), "+f"(c[3])
        : "r"(a[0]), "r"(a[1]), "r"(a[2]), "r"(a[3]), "r"(b[0]), "r"(b[1]));
}

// ---------------- mma.sync bf16x3 GEMM: C[128 x 256] tile, K=384, 512 thr ----------------
#define BM 128
#define BN 256
#define BK 32
#define KITERS (KTOT/BK)       // 12
#define AREG   10240           // 128 rows * 80 B
#define BREG   20480           // 256 rows * 80 B
#define STAGEB (2*AREG + 2*BREG)   // 61440
#define NSTAGE 3
#define GEMM_SMEM (NSTAGE*STAGEB)  // 184320

__device__ __forceinline__ void gemm_bf16x3(
    const unsigned short* __restrict__ Ah, const unsigned short* __restrict__ Al,
    const unsigned short* __restrict__ Bh, const unsigned short* __restrict__ Bl,
    float* __restrict__ Y)
{
    extern __shared__ char gsm[];
    const uint32_t smem_base = smem_u32(gsm);
    const int tid = threadIdx.x, wid = tid >> 5, lane = tid & 31;
    const int mBase = (wid >> 2) * 32;       // 4 warp-rows of 32
    const int nBase = (wid & 3) * 64;        // 4 warp-cols of 64

    const int aRow = lane & 15, aCol = lane >> 4;
    const int i16  = lane & 15;
    const int bRow = i16 & 7,  bCol = i16 >> 3;

    float acc[2][8][4];
#pragma unroll
    for (int mt = 0; mt < 2; mt++)
#pragma unroll
        for (int nt = 0; nt < 8; nt++)
#pragma unroll
            for (int q = 0; q < 4; q++) acc[mt][nt][q] = 0.f;

    // stage loader: 3072 x 16B pieces, 6 per thread
    auto load_stage = [&](int st, int k0) {
        const uint32_t sb = smem_base + (st % NSTAGE) * STAGEB;
#pragma unroll
        for (int j = 0; j < 6; j++) {
            const int idx = tid + 512 * j;
            uint32_t saddr;
            const unsigned short* gsrc;
            if (idx < 1024) {                      // A hi/lo: 128 rows x 4 chunks x 2
                const int half = idx >> 9;         // 0=hi 1=lo
                const int rem = idx & 511;
                const int r = rem >> 2, c = rem & 3;
                saddr = sb + half * AREG + r * 80 + c * 16;
                gsrc = (half ? Al : Ah) + (size_t)r * KTOT + k0 + c * 8;
            } else {                               // B hi/lo: 256 rows x 4 chunks x 2
                const int bidx = idx - 1024;
                const int half = bidx >> 10;       // 0=hi 1=lo
                const int rem = bidx & 1023;
                const int r = rem >> 2, c = rem & 3;
                saddr = sb + 2*AREG + half * BREG + r * 80 + c * 16;
                gsrc = (half ? Bl : Bh) + (size_t)r * KTOT + k0 + c * 8;
            }
            cpa16(saddr, gsrc);
        }
        asm volatile("cp.async.commit_group;" ::: "memory");
    };

#pragma unroll
    for (int st = 0; st < NSTAGE - 1; st++) load_stage(st, st * BK);

    for (int it = 0; it < KITERS; it++) {
        load_stage(it + NSTAGE - 1 < KITERS ? it + NSTAGE - 1 : it, // guard: reload current if done
                   (it + NSTAGE - 1 < KITERS ? it + NSTAGE - 1 : it) * BK);
        // NOTE: when it+NSTAGE-1 >= KITERS the redundant reload of an already-
        // consumed stage is harmless (data identical) and keeps group counts uniform.
        asm volatile("cp.async.wait_group %0;" :: "n"(NSTAGE - 1) : "memory");
        __syncthreads();

        const uint32_t sb  = smem_base + (it % NSTAGE) * STAGEB;
        const uint32_t sAh = sb, sAl = sb + AREG, sBh = sb + 2*AREG, sBl = sb + 2*AREG + BREG;

#pragma unroll
        for (int ks = 0; ks < 2; ks++) {
            const uint32_t akb = ks * 32 + aCol * 16;
            const uint32_t bkb = ks * 32 + bCol * 16;
            uint32_t fAh[2][4], fAl[2][4], fBh[8][2], fBl[8][2];
#pragma unroll
            for (int mt = 0; mt < 2; mt++)
                ldm_x4(fAh[mt], sAh + (uint32_t)(mBase + mt*16 + aRow) * 80 + akb);
#pragma unroll
            for (int nt = 0; nt < 8; nt++)
                ldm_x2(fBh[nt], sBh + (uint32_t)(nBase + nt*8 + bRow) * 80 + bkb);
#pragma unroll
            for (int mt = 0; mt < 2; mt++)
#pragma unroll
                for (int nt = 0; nt < 8; nt++) mma_bf16(acc[mt][nt], fAh[mt], fBh[nt]);
#pragma unroll
            for (int nt = 0; nt < 8; nt++)
                ldm_x2(fBl[nt], sBl + (uint32_t)(nBase + nt*8 + bRow) * 80 + bkb);
#pragma unroll
            for (int mt = 0; mt < 2; mt++)
#pragma unroll
                for (int nt = 0; nt < 8; nt++) mma_bf16(acc[mt][nt], fAh[mt], fBl[nt]);
#pragma unroll
            for (int mt = 0; mt < 2; mt++)
                ldm_x4(fAl[mt], sAl + (uint32_t)(mBase + mt*16 + aRow) * 80 + akb);
#pragma unroll
            for (int mt = 0; mt < 2; mt++)
#pragma unroll
                for (int nt = 0; nt < 8; nt++) mma_bf16(acc[mt][nt], fAl[mt], fBh[nt]);
        }
        __syncthreads();
    }

    const int gr = lane >> 2, gc = (lane & 3) * 2;
#pragma unroll
    for (int mt = 0; mt < 2; mt++) {
#pragma unroll
        for (int nt = 0; nt < 8; nt++) {
            float* d0 = Y + (size_t)(mBase + mt*16 + gr) * HWN + nBase + nt*8 + gc;
            d0[0] = acc[mt][nt][0]; d0[1] = acc[mt][nt][1];
            float* d1 = d0 + 8 * HWN;
            d1[0] = acc[mt][nt][2]; d1[1] = acc[mt][nt][3];
        }
    }
}

__global__ __launch_bounds__(512, 1)
void qkv_gemm_tc()
{
    const int z = blockIdx.z, s = z >> 2, b = z & 3;
    const int row0 = blockIdx.y * BM, n0 = blockIdx.x * BN;
    const size_t aoff = (size_t)(s * CH + row0) * KTOT;
    const int inp = (s == 0) ? 1 : 0;   // q comes from message
    const size_t boff = ((size_t)(inp * BATCH + b) * HWN + n0) * KTOT;
    float* Y = g_pre + ((size_t)z * CH + row0) * HWN + n0;
    gemm_bf16x3(g_wh + aoff, g_wl + aoff, g_inth + boff, g_intl + boff, Y);
}

__global__ __launch_bounds__(512, 1)
void proj_gemm_tc(float* __restrict__ out)
{
    const int b = blockIdx.z;
    const int row0 = blockIdx.y * BM, n0 = blockIdx.x * BN;
    const size_t aoff = (size_t)(1152 + row0) * KTOT;
    const size_t boff = ((size_t)b * HWN + n0) * KTOT;
    float* Y = out + ((size_t)b * CH + row0) * HWN + n0;
    gemm_bf16x3(g_wh + aoff, g_wl + aoff, g_avh + boff, g_avl + boff, Y);
}

// ---------------- convert weights to bf16 hi/lo ----------------
__global__ __launch_bounds__(256) void wconv_kernel(const float* __restrict__ wqkv,
                                                    const float* __restrict__ wproj)
{
    const size_t i = (size_t)blockIdx.x * 256 + threadIdx.x;
    const float f = (i < (size_t)1152 * KTOT) ? wqkv[i] : wproj[i - (size_t)1152 * KTOT];
    const uint32_t bits = __float_as_uint(f);
    const float hi = __uint_as_float(bits & 0xFFFF0000u);
    const __nv_bfloat16 lo = __float2bfloat16(f - hi);
    g_wh[i] = (unsigned short)(bits >> 16);
    g_wl[i] = *(const unsigned short*)&lo;
}

// ---------------- transpose + convert inputs ----------------
__global__ __launch_bounds__(256) void trx_kernel(const float* __restrict__ x,
                                                  const float* __restrict__ msg)
{
    __shared__ float t[32][33];
    const int z = blockIdx.z, inp = z >> 2, b = z & 3;
    const int p0 = blockIdx.x * 32, c0 = blockIdx.y * 32;
    const int tx = threadIdx.x, ty = threadIdx.y;
    const float* src = (inp ? msg : x) + ((size_t)b * CH + c0) * HWN + p0;
    for (int yy = ty; yy < 32; yy += 8) t[yy][tx] = src[(size_t)yy * HWN + tx];
    __syncthreads();
    unsigned short* dh = g_inth + ((size_t)z * HWN + p0) * CH + c0;
    unsigned short* dl = g_intl + ((size_t)z * HWN + p0) * CH + c0;
    for (int yy = ty; yy < 32; yy += 8) {
        const float f = t[tx][yy];
        const uint32_t bits = __float_as_uint(f);
        const float hi = __uint_as_float(bits & 0xFFFF0000u);
        const __nv_bfloat16 lo = __float2bfloat16(f - hi);
        dh[(size_t)yy * CH + tx] = (unsigned short)(bits >> 16);
        dl[(size_t)yy * CH + tx] = *(const unsigned short*)&lo;
    }
}

// ---------------- depthwise 3x3: 4 px/thread + fused sqnorm partials ----------------
__global__ __launch_bounds__(256)
void dwconv_kernel(const float* __restrict__ wdw)
{
    __shared__ float red[8];

    const int zc = blockIdx.z;
    const int z  = zc / CH;
    const int c  = zc % CH;
    const int s  = z / BATCH;
    const float* wk = wdw + (size_t)(s*CH + c) * 9;
    const float* in   = g_pre  + (size_t)zc * HWN;
    float*       outp = g_post + (size_t)zc * HWN;

    float w[9];
#pragma unroll
    for (int i = 0; i < 9; i++) w[i] = __ldg(&wk[i]);

    const int tx = threadIdx.x;
    const int ty = threadIdx.y;
    const int px0 = tx * 4;
    const int py  = blockIdx.y * 8 + ty;

    float r[3][6];
#pragma unroll
    for (int ky = 0; ky < 3; ky++) {
        const int iy = py + ky - 1;
        if (iy < 0 || iy >= IMG) {
#pragma unroll
            for (int e = 0; e < 6; e++) r[ky][e] = 0.f;
        } else {
            const float* base = in + (size_t)iy * IMG + px0;
            const float4 v = *(const float4*)base;
            r[ky][1] = v.x; r[ky][2] = v.y; r[ky][3] = v.z; r[ky][4] = v.w;
            r[ky][0] = (px0 > 0)       ? __ldg(base - 1) : 0.f;
            r[ky][5] = (px0 + 4 < IMG) ? __ldg(base + 4) : 0.f;
        }
    }

    float a0 = 0.f, a1 = 0.f, a2 = 0.f, a3 = 0.f;
#pragma unroll
    for (int ky = 0; ky < 3; ky++) {
#pragma unroll
        for (int kx = 0; kx < 3; kx++) {
            const float wv = w[ky*3 + kx];
            a0 += r[ky][0 + kx] * wv;
            a1 += r[ky][1 + kx] * wv;
            a2 += r[ky][2 + kx] * wv;
            a3 += r[ky][3 + kx] * wv;
        }
    }
    *(float4*)(outp + (size_t)py * IMG + px0) = make_float4(a0, a1, a2, a3);

    float loc = a0*a0 + a1*a1 + a2*a2 + a3*a3;
    const int tid = ty * 32 + tx;
#pragma unroll
    for (int o = 16; o > 0; o >>= 1) loc += __shfl_xor_sync(0xffffffffu, loc, o);
    if ((tid & 31) == 0) red[tid >> 5] = loc;
    __syncthreads();
    if (tid == 0 && s < 2) {
        float t = 0.f;
#pragma unroll
        for (int i = 0; i < 8; i++) t += red[i];
        g_snp[(size_t)zc * 16 + blockIdx.y] = t;
    }
}

// ---------------- reduce sqnorm partials ----------------
__global__ __launch_bounds__(256)
void sqnorm_kernel()
{
    const int r = blockIdx.x * 256 + threadIdx.x;
    if (r >= 2*BATCH*CH) return;
    float s = 0.f;
#pragma unroll
    for (int i = 0; i < 16; i++) s += g_snp[(size_t)r * 16 + i];
    g_sqn[r] = s;
}

// ---------------- Gram partials ----------------
__global__ __launch_bounds__(256)
void gram_kernel()
{
    __shared__ __align__(16) float qs[48][65];
    __shared__ __align__(16) float ks[48][65];

    const int bh = blockIdx.y;
    const int b  = bh >> 3;
    const int h  = bh & 7;
    const int n0 = blockIdx.x * NCHUNK;
    const float* qbase = g_post + ((size_t)(0*BATCH + b)*CH + h*HD) * HWN;
    const float* kbase = g_post + ((size_t)(1*BATCH + b)*CH + h*HD) * HWN;
    const int tid = threadIdx.y * 16 + threadIdx.x;

    float acc[3][3];
#pragma unroll
    for (int r = 0; r < 3; r++)
#pragma unroll
        for (int c = 0; c < 3; c++) acc[r][c] = 0.f;

    const int i0 = threadIdx.y * 3;
    const int j0 = threadIdx.x * 3;

    for (int t = 0; t < NCHUNK; t += 64) {
        for (int e = tid; e < 48*64; e += 256) {
            const int i = e >> 6, j = e & 63;
            qs[i][j] = qbase[(size_t)i*HWN + n0 + t + j];
            ks[i][j] = kbase[(size_t)i*HWN + n0 + t + j];
        }
        __syncthreads();
#pragma unroll 8
        for (int nn = 0; nn < 64; nn++) {
            const float q0 = qs[i0+0][nn], q1 = qs[i0+1][nn], q2 = qs[i0+2][nn];
            const float k0 = ks[j0+0][nn], k1 = ks[j0+1][nn], k2 = ks[j0+2][nn];
            acc[0][0] += q0*k0; acc[0][1] += q0*k1; acc[0][2] += q0*k2;
            acc[1][0] += q1*k0; acc[1][1] += q1*k1; acc[1][2] += q1*k2;
            acc[2][0] += q2*k0; acc[2][1] += q2*k1; acc[2][2] += q2*k2;
        }
        __syncthreads();
    }

    float* gp = g_gpart + ((size_t)blockIdx.x * NBH + bh) * (HD*HD);
#pragma unroll
    for (int r = 0; r < 3; r++)
#pragma unroll
        for (int c = 0; c < 3; c++)
            gp[(i0+r)*HD + (j0+c)] = acc[r][c];
}

__global__ __launch_bounds__(1024)
void gram_reduce_kernel()
{
    const int idx = blockIdx.x * 1024 + threadIdx.x;
    float s = 0.f;
#pragma unroll
    for (int ch = 0; ch < GRAM_CHUNKS; ch++)
        s += g_gpart[(size_t)ch * NBH * (HD*HD) + idx];
    g_gram[idx] = s;
}

// ---------------- normalize + temperature + softmax ----------------
__global__ __launch_bounds__(64)
void softmax_kernel(const float* __restrict__ temp)
{
    const int bh = blockIdx.x;
    const int b  = bh >> 3;
    const int h  = bh & 7;
    const int i  = threadIdx.x;
    if (i >= HD) return;

    float* gg = g_gram + (size_t)bh * (HD*HD) + i*HD;
    const float invq = rsqrtf(fmaxf(g_sqn[b*CH + h*HD + i], 1e-24f));
    const float T = temp[h];

    float row[HD];
    float m = -3.4e38f;
#pragma unroll
    for (int j = 0; j < HD; j++) {
        const float invk = rsqrtf(fmaxf(g_sqn[(BATCH + b)*CH + h*HD + j], 1e-24f));
        const float v = gg[j] * invq * invk * T;
        row[j] = v;
        m = fmaxf(m, v);
    }
    float sum = 0.f;
#pragma unroll
    for (int j = 0; j < HD; j++) { row[j] = expf(row[j] - m); sum += row[j]; }
    const float inv = 1.f / sum;
#pragma unroll
    for (int j = 0; j < HD; j++) gg[j] = row[j] * inv;
}

// ---------------- A@V, writing bf16 hi/lo transposed [b][p][c] ----------------
__global__ __launch_bounds__(256)
void av_kernel()
{
    __shared__ __align__(16) float As[HD*HD];
    const int bh = blockIdx.y;
    const int b  = bh >> 3;
    const int h  = bh & 7;
    const int tid = threadIdx.x;
    const int n = blockIdx.x * 256 + tid;

    for (int e = tid; e < HD*HD; e += 256) As[e] = g_gram[(size_t)bh * (HD*HD) + e];
    __syncthreads();

    const float* vbase = g_post + ((size_t)(2*BATCH + b)*CH + h*HD) * HWN + n;
    float acc[HD];
#pragma unroll
    for (int i = 0; i < HD; i++) acc[i] = 0.f;

#pragma unroll 4
    for (int j = 0; j < HD; j++) {
        const float vj = __ldg(&vbase[(size_t)j * HWN]);
#pragma unroll
        for (int i = 0; i < HD; i++) acc[i] += As[i*HD + j] * vj;
    }

    unsigned short* dh = g_avh + ((size_t)b * HWN + n) * CH + h*HD;
    unsigned short* dl = g_avl + ((size_t)b * HWN + n) * CH + h*HD;
#pragma unroll
    for (int i = 0; i < HD; i++) {
        const uint32_t bits = __float_as_uint(acc[i]);
        const float hi = __uint_as_float(bits & 0xFFFF0000u);
        const __nv_bfloat16 lo = __float2bfloat16(acc[i] - hi);
        dh[i] = (unsigned short)(bits >> 16);
        dl[i] = *(const unsigned short*)&lo;
    }
}

// ---------------- launch ----------------
extern "C" void kernel_launch(void* const* d_in, const int* in_sizes, int n_in,
                              void* d_out, int out_size)
{
    const float* x      = (const float*)d_in[0];
    const float* msg    = (const float*)d_in[1];
    const float* w_qkv  = (const float*)d_in[2];
    const float* w_dw   = (const float*)d_in[3];
    const float* w_proj = (const float*)d_in[4];
    const float* temp   = (const float*)d_in[5];
    float* out = (float*)d_out;

    cudaFuncSetAttribute(qkv_gemm_tc, cudaFuncAttributeMaxDynamicSharedMemorySize, GEMM_SMEM);
    cudaFuncSetAttribute(proj_gemm_tc, cudaFuncAttributeMaxDynamicSharedMemorySize, GEMM_SMEM);

    // 0. bf16 hi/lo conversions
    wconv_kernel<<<(1536*KTOT)/256, 256>>>(w_qkv, w_proj);
    trx_kernel<<<dim3(HWN/32, CH/32, 2*BATCH), dim3(32,8)>>>(x, msg);
    // 1. qkv GEMMs on tensor cores (mma.sync bf16x3 split, 128x256 tiles)
    qkv_gemm_tc<<<dim3(HWN/BN, CH/BM, 3*BATCH), 512, GEMM_SMEM>>>();
    // 2. depthwise 3x3 (4 px/thread, fused sqnorm partials)
    dwconv_kernel<<<dim3(1, IMG/8, 3*BATCH*CH), dim3(32,8)>>>(w_dw);
    // 3. reduce sqnorm partials
    sqnorm_kernel<<<(2*BATCH*CH + 255)/256, 256>>>();
    // 4-5. Gram (two-phase deterministic)
    gram_kernel<<<dim3(GRAM_CHUNKS, NBH), dim3(16,16)>>>();
    gram_reduce_kernel<<<(NBH*HD*HD)/1024, 1024>>>();
    // 6. softmax
    softmax_kernel<<<NBH, 64>>>(temp);
    // 7. A@V (emits bf16 hi/lo, transposed)
    av_kernel<<<dim3(HWN/256, NBH), 256>>>();
    // 8. output projection on tensor cores
    proj_gemm_tc<<<dim3(HWN/BN, CH/BM, BATCH), 512, GEMM_SMEM>>>(out);
}

// round 9
// speedup vs baseline: 1.0438x; 1.0438x over previous
#include <cuda_runtime.h>
#include <cuda_bf16.h>
#include <math.h>
#include <stdint.h>

#define BATCH 4
#define CH    384
#define IMG   128
#define HWN   (IMG*IMG)      // 16384
#define NH    8
#define HD    48
#define NBH   (BATCH*NH)     // 32
#define GRAM_CHUNKS 32
#define NCHUNK (HWN/GRAM_CHUNKS)
#define KTOT  384

// ---------------- scratch (device globals; no allocation) ----------------
__device__ __align__(16) float g_pre  [3ull*BATCH*CH*HWN];
__device__ __align__(16) float g_post [3ull*BATCH*CH*HWN];
__device__ __align__(16) float g_snp  [2*BATCH*CH*16];
__device__ __align__(16) float g_sqn  [2*BATCH*CH];
__device__ __align__(16) float g_gpart[(size_t)GRAM_CHUNKS*NBH*HD*HD];
__device__ __align__(16) float g_gram [NBH*HD*HD];
// bf16 split operands
__device__ __align__(16) unsigned short g_wh  [(size_t)1536*KTOT];
__device__ __align__(16) unsigned short g_wl  [(size_t)1536*KTOT];
__device__ __align__(16) unsigned short g_inth[(size_t)2*BATCH*HWN*CH];  // [inp][b][p][c]
__device__ __align__(16) unsigned short g_intl[(size_t)2*BATCH*HWN*CH];
__device__ __align__(16) unsigned short g_avh [(size_t)BATCH*HWN*CH];    // [b][p][c]
__device__ __align__(16) unsigned short g_avl [(size_t)BATCH*HWN*CH];

// ---------------- PTX helpers (sm_80-level only) ----------------
__device__ __forceinline__ uint32_t smem_u32(const void* p) {
    uint32_t a;
    asm("{ .reg .u64 t; cvta.to.shared.u64 t, %1; cvt.u32.u64 %0, t; }" : "=r"(a) : "l"(p));
    return a;
}
__device__ __forceinline__ void cpa16(uint32_t saddr, const void* gptr) {
    asm volatile("cp.async.cg.shared.global [%0], [%1], 16;" :: "r"(saddr), "l"(gptr));
}
__device__ __forceinline__ void ldm_x4(uint32_t* r, uint32_t addr) {
    asm volatile("ldmatrix.sync.aligned.m8n8.x4.shared.b16 {%0,%1,%2,%3}, [%4];"
        : "=r"(r[0]), "=r"(r[1]), "=r"(r[2]), "=r"(r[3]) : "r"(addr));
}
__device__ __forceinline__ void ldm_x2(uint32_t* r, uint32_t addr) {
    asm volatile("ldmatrix.sync.aligned.m8n8.x2.shared.b16 {%0,%1}, [%2];"
        : "=r"(r[0]), "=r"(r[1]) : "r"(addr));
}
__device__ __forceinline__ void mma_bf16(float* c, const uint32_t* a, const uint32_t* b) {
    asm volatile("mma.sync.aligned.m16n8k16.row.col.f32.bf16.bf16.f32 "
        "{%0,%1,%2,%3}, {%4,%5,%6,%7}, {%8,%9}, {%0,%1,%2,%3};"
        : "+f"(c[0]), "+f"(c[1]), "+f"(c[2]), "+f"(c[3])
        : "r"(a[0]), "r"(a[1]), "r"(a[2]), "r"(a[3]), "r"(b[0]), "r"(b[1]));
}

// ---------------- mma.sync bf16x3 GEMM: C[128 x 128] tile, K=384 (R7 config) ----------------
#define BM 128
#define BN 128
#define BK 32
#define KITERS (KTOT/BK)       // 12
#define REGB   10240
#define STAGEB 40960
#define GEMM_SMEM (2*STAGEB)   // 81920

__device__ __forceinline__ void gemm_bf16x3(
    const unsigned short* __restrict__ Ah, const unsigned short* __restrict__ Al,
    const unsigned short* __restrict__ Bh, const unsigned short* __restrict__ Bl,
    float* __restrict__ Y)
{
    extern __shared__ char gsm[];
    const uint32_t smem_base = smem_u32(gsm);
    const int tid = threadIdx.x, wid = tid >> 5, lane = tid & 31;
    const int mBase = (wid >> 2) * 64;       // 2 warp-rows
    const int nBase = (wid & 3) * 32;        // 4 warp-cols

    const int aRow = lane & 15, aCol = lane >> 4;
    const int i16  = lane & 15;
    const int bRow = i16 & 7,  bCol = i16 >> 3;

    float acc[4][4][4];
#pragma unroll
    for (int mt = 0; mt < 4; mt++)
#pragma unroll
        for (int nt = 0; nt < 4; nt++)
#pragma unroll
            for (int q = 0; q < 4; q++) acc[mt][nt][q] = 0.f;

    auto load_stage = [&](int st, int k0) {
        const uint32_t sb = smem_base + (st & 1) * STAGEB;
#pragma unroll
        for (int j = 0; j < 8; j++) {
            const int idx = tid + 256 * j;
            const int region = idx >> 9;
            const int rem = idx & 511;
            const int r = rem >> 2, c = rem & 3;
            const uint32_t saddr = sb + region * REGB + r * 80 + c * 16;
            const unsigned short* gsrc;
            if      (region == 0) gsrc = Ah + (size_t)r * KTOT + k0 + c * 8;
            else if (region == 1) gsrc = Al + (size_t)r * KTOT + k0 + c * 8;
            else if (region == 2) gsrc = Bh + (size_t)r * KTOT + k0 + c * 8;
            else                  gsrc = Bl + (size_t)r * KTOT + k0 + c * 8;
            cpa16(saddr, gsrc);
        }
        asm volatile("cp.async.commit_group;" ::: "memory");
    };

    load_stage(0, 0);

    for (int it = 0; it < KITERS; it++) {
        if (it + 1 < KITERS) {
            load_stage(it + 1, (it + 1) * BK);
            asm volatile("cp.async.wait_group 1;" ::: "memory");
        } else {
            asm volatile("cp.async.wait_group 0;" ::: "memory");
        }
        __syncthreads();

        const uint32_t sb  = smem_base + (it & 1) * STAGEB;
        const uint32_t sAh = sb, sAl = sb + REGB, sBh = sb + 2*REGB, sBl = sb + 3*REGB;

#pragma unroll
        for (int ks = 0; ks < 2; ks++) {
            const uint32_t akb = ks * 32 + aCol * 16;
            const uint32_t bkb = ks * 32 + bCol * 16;
            uint32_t fAh[4][4], fAl[4][4], fBh[4][2], fBl[4][2];
#pragma unroll
            for (int mt = 0; mt < 4; mt++)
                ldm_x4(fAh[mt], sAh + (uint32_t)(mBase + mt*16 + aRow) * 80 + akb);
#pragma unroll
            for (int nt = 0; nt < 4; nt++)
                ldm_x2(fBh[nt], sBh + (uint32_t)(nBase + nt*8 + bRow) * 80 + bkb);
#pragma unroll
            for (int mt = 0; mt < 4; mt++)
#pragma unroll
                for (int nt = 0; nt < 4; nt++) mma_bf16(acc[mt][nt], fAh[mt], fBh[nt]);
#pragma unroll
            for (int nt = 0; nt < 4; nt++)
                ldm_x2(fBl[nt], sBl + (uint32_t)(nBase + nt*8 + bRow) * 80 + bkb);
#pragma unroll
            for (int mt = 0; mt < 4; mt++)
#pragma unroll
                for (int nt = 0; nt < 4; nt++) mma_bf16(acc[mt][nt], fAh[mt], fBl[nt]);
#pragma unroll
            for (int mt = 0; mt < 4; mt++)
                ldm_x4(fAl[mt], sAl + (uint32_t)(mBase + mt*16 + aRow) * 80 + akb);
#pragma unroll
            for (int mt = 0; mt < 4; mt++)
#pragma unroll
                for (int nt = 0; nt < 4; nt++) mma_bf16(acc[mt][nt], fAl[mt], fBh[nt]);
        }
        __syncthreads();
    }

    const int gr = lane >> 2, gc = (lane & 3) * 2;
#pragma unroll
    for (int mt = 0; mt < 4; mt++) {
#pragma unroll
        for (int nt = 0; nt < 4; nt++) {
            float* d0 = Y + (size_t)(mBase + mt*16 + gr) * HWN + nBase + nt*8 + gc;
            d0[0] = acc[mt][nt][0]; d0[1] = acc[mt][nt][1];
            float* d1 = d0 + 8 * HWN;
            d1[0] = acc[mt][nt][2]; d1[1] = acc[mt][nt][3];
        }
    }
}

__global__ __launch_bounds__(256, 1)
void qkv_gemm_tc()
{
    const int z = blockIdx.z, s = z >> 2, b = z & 3;
    const int row0 = blockIdx.y * BM, n0 = blockIdx.x * BN;
    const size_t aoff = (size_t)(s * CH + row0) * KTOT;
    const int inp = (s == 0) ? 1 : 0;   // q comes from message
    const size_t boff = ((size_t)(inp * BATCH + b) * HWN + n0) * KTOT;
    float* Y = g_pre + ((size_t)z * CH + row0) * HWN + n0;
    gemm_bf16x3(g_wh + aoff, g_wl + aoff, g_inth + boff, g_intl + boff, Y);
}

__global__ __launch_bounds__(256, 1)
void proj_gemm_tc(float* __restrict__ out)
{
    const int b = blockIdx.z;
    const int row0 = blockIdx.y * BM, n0 = blockIdx.x * BN;
    const size_t aoff = (size_t)(1152 + row0) * KTOT;
    const size_t boff = ((size_t)b * HWN + n0) * KTOT;
    float* Y = out + ((size_t)b * CH + row0) * HWN + n0;
    gemm_bf16x3(g_wh + aoff, g_wl + aoff, g_avh + boff, g_avl + boff, Y);
}

// ---------------- convert weights to bf16 hi/lo ----------------
__global__ __launch_bounds__(256) void wconv_kernel(const float* __restrict__ wqkv,
                                                    const float* __restrict__ wproj)
{
    const size_t i = (size_t)blockIdx.x * 256 + threadIdx.x;
    const float f = (i < (size_t)1152 * KTOT) ? wqkv[i] : wproj[i - (size_t)1152 * KTOT];
    const uint32_t bits = __float_as_uint(f);
    const float hi = __uint_as_float(bits & 0xFFFF0000u);
    const __nv_bfloat16 lo = __float2bfloat16(f - hi);
    g_wh[i] = (unsigned short)(bits >> 16);
    g_wl[i] = *(const unsigned short*)&lo;
}

// ---------------- transpose + convert one input: [b][c][p] -> [inp][b][p][c] hi/lo ----------------
__global__ __launch_bounds__(256) void trx_kernel(const float* __restrict__ src0, int inp)
{
    __shared__ float t[32][33];
    const int b = blockIdx.z;
    const int p0 = blockIdx.x * 32, c0 = blockIdx.y * 32;
    const int tx = threadIdx.x, ty = threadIdx.y;
    const float* src = src0 + ((size_t)b * CH + c0) * HWN + p0;
    for (int yy = ty; yy < 32; yy += 8) t[yy][tx] = src[(size_t)yy * HWN + tx];
    __syncthreads();
    const int z = inp * BATCH + b;
    unsigned short* dh = g_inth + ((size_t)z * HWN + p0) * CH + c0;
    unsigned short* dl = g_intl + ((size_t)z * HWN + p0) * CH + c0;
    for (int yy = ty; yy < 32; yy += 8) {
        const float f = t[tx][yy];
        const uint32_t bits = __float_as_uint(f);
        const float hi = __uint_as_float(bits & 0xFFFF0000u);
        const __nv_bfloat16 lo = __float2bfloat16(f - hi);
        dh[(size_t)yy * CH + tx] = (unsigned short)(bits >> 16);
        dl[(size_t)yy * CH + tx] = *(const unsigned short*)&lo;
    }
}

// ---------------- depthwise 3x3: 4 px/thread + fused sqnorm partials ----------------
__global__ __launch_bounds__(256)
void dwconv_kernel(const float* __restrict__ wdw)
{
    __shared__ float red[8];

    const int zc = blockIdx.z;
    const int z  = zc / CH;
    const int c  = zc % CH;
    const int s  = z / BATCH;
    const float* wk = wdw + (size_t)(s*CH + c) * 9;
    const float* in   = g_pre  + (size_t)zc * HWN;
    float*       outp = g_post + (size_t)zc * HWN;

    float w[9];
#pragma unroll
    for (int i = 0; i < 9; i++) w[i] = __ldg(&wk[i]);

    const int tx = threadIdx.x;
    const int ty = threadIdx.y;
    const int px0 = tx * 4;
    const int py  = blockIdx.y * 8 + ty;

    float r[3][6];
#pragma unroll
    for (int ky = 0; ky < 3; ky++) {
        const int iy = py + ky - 1;
        if (iy < 0 || iy >= IMG) {
#pragma unroll
            for (int e = 0; e < 6; e++) r[ky][e] = 0.f;
        } else {
            const float* base = in + (size_t)iy * IMG + px0;
            const float4 v = *(const float4*)base;
            r[ky][1] = v.x; r[ky][2] = v.y; r[ky][3] = v.z; r[ky][4] = v.w;
            r[ky][0] = (px0 > 0)       ? __ldg(base - 1) : 0.f;
            r[ky][5] = (px0 + 4 < IMG) ? __ldg(base + 4) : 0.f;
        }
    }

    float a0 = 0.f, a1 = 0.f, a2 = 0.f, a3 = 0.f;
#pragma unroll
    for (int ky = 0; ky < 3; ky++) {
#pragma unroll
        for (int kx = 0; kx < 3; kx++) {
            const float wv = w[ky*3 + kx];
            a0 += r[ky][0 + kx] * wv;
            a1 += r[ky][1 + kx] * wv;
            a2 += r[ky][2 + kx] * wv;
            a3 += r[ky][3 + kx] * wv;
        }
    }
    *(float4*)(outp + (size_t)py * IMG + px0) = make_float4(a0, a1, a2, a3);

    float loc = a0*a0 + a1*a1 + a2*a2 + a3*a3;
    const int tid = ty * 32 + tx;
#pragma unroll
    for (int o = 16; o > 0; o >>= 1) loc += __shfl_xor_sync(0xffffffffu, loc, o);
    if ((tid & 31) == 0) red[tid >> 5] = loc;
    __syncthreads();
    if (tid == 0 && s < 2) {
        float t = 0.f;
#pragma unroll
        for (int i = 0; i < 8; i++) t += red[i];
        g_snp[(size_t)zc * 16 + blockIdx.y] = t;
    }
}

// ---------------- reduce sqnorm partials ----------------
__global__ __launch_bounds__(256)
void sqnorm_kernel()
{
    const int r = blockIdx.x * 256 + threadIdx.x;
    if (r >= 2*BATCH*CH) return;
    float s = 0.f;
#pragma unroll
    for (int i = 0; i < 16; i++) s += g_snp[(size_t)r * 16 + i];
    g_sqn[r] = s;
}

// ---------------- Gram partials: 8x8 threads, 6x6 per thread ----------------
__global__ __launch_bounds__(64)
void gram_kernel()
{
    __shared__ __align__(16) float qs[48][65];
    __shared__ __align__(16) float ks[48][65];

    const int bh = blockIdx.y;
    const int b  = bh >> 3;
    const int h  = bh & 7;
    const int n0 = blockIdx.x * NCHUNK;
    const float* qbase = g_post + ((size_t)(0*BATCH + b)*CH + h*HD) * HWN;
    const float* kbase = g_post + ((size_t)(1*BATCH + b)*CH + h*HD) * HWN;
    const int tid = threadIdx.y * 8 + threadIdx.x;
    const int i0 = threadIdx.y * 6;
    const int j0 = threadIdx.x * 6;

    float acc[6][6];
#pragma unroll
    for (int r = 0; r < 6; r++)
#pragma unroll
        for (int c = 0; c < 6; c++) acc[r][c] = 0.f;

    for (int t = 0; t < NCHUNK; t += 64) {
        // load 48x64 q and k: float4 global reads, scalar smem writes
        for (int e = tid; e < 48*16; e += 64) {
            const int i = e >> 4, j4 = (e & 15) * 4;
            const float4 qv = *(const float4*)&qbase[(size_t)i*HWN + n0 + t + j4];
            const float4 kv = *(const float4*)&kbase[(size_t)i*HWN + n0 + t + j4];
            qs[i][j4+0] = qv.x; qs[i][j4+1] = qv.y; qs[i][j4+2] = qv.z; qs[i][j4+3] = qv.w;
            ks[i][j4+0] = kv.x; ks[i][j4+1] = kv.y; ks[i][j4+2] = kv.z; ks[i][j4+3] = kv.w;
        }
        __syncthreads();
#pragma unroll 4
        for (int nn = 0; nn < 64; nn++) {
            float q[6], k[6];
#pragma unroll
            for (int r = 0; r < 6; r++) q[r] = qs[i0+r][nn];
#pragma unroll
            for (int c = 0; c < 6; c++) k[c] = ks[j0+c][nn];
#pragma unroll
            for (int r = 0; r < 6; r++)
#pragma unroll
                for (int c = 0; c < 6; c++) acc[r][c] += q[r] * k[c];
        }
        __syncthreads();
    }

    float* gp = g_gpart + ((size_t)blockIdx.x * NBH + bh) * (HD*HD);
#pragma unroll
    for (int r = 0; r < 6; r++)
#pragma unroll
        for (int c = 0; c < 6; c++)
            gp[(i0+r)*HD + (j0+c)] = acc[r][c];
}

__global__ __launch_bounds__(1024)
void gram_reduce_kernel()
{
    const int idx = blockIdx.x * 1024 + threadIdx.x;
    float s = 0.f;
#pragma unroll
    for (int ch = 0; ch < GRAM_CHUNKS; ch++)
        s += g_gpart[(size_t)ch * NBH * (HD*HD) + idx];
    g_gram[idx] = s;
}

// ---------------- normalize + temperature + softmax ----------------
__global__ __launch_bounds__(64)
void softmax_kernel(const float* __restrict__ temp)
{
    const int bh = blockIdx.x;
    const int b  = bh >> 3;
    const int h  = bh & 7;
    const int i  = threadIdx.x;
    if (i >= HD) return;

    float* gg = g_gram + (size_t)bh * (HD*HD) + i*HD;
    const float invq = rsqrtf(fmaxf(g_sqn[b*CH + h*HD + i], 1e-24f));
    const float T = temp[h];

    float row[HD];
    float m = -3.4e38f;
#pragma unroll
    for (int j = 0; j < HD; j++) {
        const float invk = rsqrtf(fmaxf(g_sqn[(BATCH + b)*CH + h*HD + j], 1e-24f));
        const float v = gg[j] * invq * invk * T;
        row[j] = v;
        m = fmaxf(m, v);
    }
    float sum = 0.f;
#pragma unroll
    for (int j = 0; j < HD; j++) { row[j] = expf(row[j] - m); sum += row[j]; }
    const float inv = 1.f / sum;
#pragma unroll
    for (int j = 0; j < HD; j++) gg[j] = row[j] * inv;
}

// ---------------- A@V, writing bf16 hi/lo transposed [b][p][c] ----------------
__global__ __launch_bounds__(256)
void av_kernel()
{
    __shared__ __align__(16) float As[HD*HD];
    const int bh = blockIdx.y;
    const int b  = bh >> 3;
    const int h  = bh & 7;
    const int tid = threadIdx.x;
    const int n = blockIdx.x * 256 + tid;

    for (int e = tid; e < HD*HD; e += 256) As[e] = g_gram[(size_t)bh * (HD*HD) + e];
    __syncthreads();

    const float* vbase = g_post + ((size_t)(2*BATCH + b)*CH + h*HD) * HWN + n;
    float acc[HD];
#pragma unroll
    for (int i = 0; i < HD; i++) acc[i] = 0.f;

#pragma unroll 4
    for (int j = 0; j < HD; j++) {
        const float vj = __ldg(&vbase[(size_t)j * HWN]);
#pragma unroll
        for (int i = 0; i < HD; i++) acc[i] += As[i*HD + j] * vj;
    }

    unsigned short* dh = g_avh + ((size_t)b * HWN + n) * CH + h*HD;
    unsigned short* dl = g_avl + ((size_t)b * HWN + n) * CH + h*HD;
#pragma unroll
    for (int i = 0; i < HD; i++) {
        const uint32_t bits = __float_as_uint(acc[i]);
        const float hi = __uint_as_float(bits & 0xFFFF0000u);
        const __nv_bfloat16 lo = __float2bfloat16(acc[i] - hi);
        dh[i] = (unsigned short)(bits >> 16);
        dl[i] = *(const unsigned short*)&lo;
    }
}

// ---------------- launch ----------------
extern "C" void kernel_launch(void* const* d_in, const int* in_sizes, int n_in,
                              void* d_out, int out_size)
{
    const float* x      = (const float*)d_in[0];
    const float* msg    = (const float*)d_in[1];
    const float* w_qkv  = (const float*)d_in[2];
    const float* w_dw   = (const float*)d_in[3];
    const float* w_proj = (const float*)d_in[4];
    const float* temp   = (const float*)d_in[5];
    float* out = (float*)d_out;

    cudaFuncSetAttribute(qkv_gemm_tc, cudaFuncAttributeMaxDynamicSharedMemorySize, GEMM_SMEM);
    cudaFuncSetAttribute(proj_gemm_tc, cudaFuncAttributeMaxDynamicSharedMemorySize, GEMM_SMEM);

    // 0. bf16 hi/lo conversions (trx split so qkv_gemm is launch #4 for ncu)
    wconv_kernel<<<(1536*KTOT)/256, 256>>>(w_qkv, w_proj);
    trx_kernel<<<dim3(HWN/32, CH/32, BATCH), dim3(32,8)>>>(x, 0);
    trx_kernel<<<dim3(HWN/32, CH/32, BATCH), dim3(32,8)>>>(msg, 1);
    // 1. qkv GEMMs on tensor cores (mma.sync bf16x3 split)
    qkv_gemm_tc<<<dim3(HWN/BN, CH/BM, 3*BATCH), 256, GEMM_SMEM>>>();
    // 2. depthwise 3x3 (4 px/thread, fused sqnorm partials)
    dwconv_kernel<<<dim3(1, IMG/8, 3*BATCH*CH), dim3(32,8)>>>(w_dw);
    // 3. reduce sqnorm partials
    sqnorm_kernel<<<(2*BATCH*CH + 255)/256, 256>>>();
    // 4-5. Gram (two-phase deterministic, 6x6 register tiles)
    gram_kernel<<<dim3(GRAM_CHUNKS, NBH), dim3(8,8)>>>();
    gram_reduce_kernel<<<(NBH*HD*HD)/1024, 1024>>>();
    // 6. softmax
    softmax_kernel<<<NBH, 64>>>(temp);
    // 7. A@V (emits bf16 hi/lo, transposed)
    av_kernel<<<dim3(HWN/256, NBH), 256>>>();
    // 8. output projection on tensor cores
    proj_gemm_tc<<<dim3(HWN/BN, CH/BM, BATCH), 256, GEMM_SMEM>>>(out);
}

// round 10
// speedup vs baseline: 1.1579x; 1.1093x over previous
#include <cuda_runtime.h>
#include <cuda_bf16.h>
#include <math.h>
#include <stdint.h>

#define BATCH 4
#define CH    384
#define IMG   128
#define HWN   (IMG*IMG)      // 16384
#define NH    8
#define HD    48
#define NBH   (BATCH*NH)     // 32
#define GRAM_CHUNKS 32
#define NCHUNK (HWN/GRAM_CHUNKS)
#define KTOT  384

// ---------------- scratch (device globals; no allocation) ----------------
__device__ __align__(16) float g_pre  [3ull*BATCH*CH*HWN];
__device__ __align__(16) float g_post [3ull*BATCH*CH*HWN];
__device__ __align__(16) float g_snp  [2*BATCH*CH*16];
__device__ __align__(16) float g_sqn  [2*BATCH*CH];
__device__ __align__(16) float g_gpart[(size_t)GRAM_CHUNKS*NBH*HD*HD];
__device__ __align__(16) float g_gram [NBH*HD*HD];
// bf16 split operands
__device__ __align__(16) unsigned short g_wh  [(size_t)1536*KTOT];
__device__ __align__(16) unsigned short g_wl  [(size_t)1536*KTOT];
__device__ __align__(16) unsigned short g_inth[(size_t)2*BATCH*HWN*CH];  // [inp][b][p][c]
__device__ __align__(16) unsigned short g_intl[(size_t)2*BATCH*HWN*CH];
__device__ __align__(16) unsigned short g_avh [(size_t)BATCH*HWN*CH];    // [b][p][c]
__device__ __align__(16) unsigned short g_avl [(size_t)BATCH*HWN*CH];

// ---------------- PTX helpers (sm_80-level only) ----------------
__device__ __forceinline__ uint32_t smem_u32(const void* p) {
    uint32_t a;
    asm("{ .reg .u64 t; cvta.to.shared.u64 t, %1; cvt.u32.u64 %0, t; }" : "=r"(a) : "l"(p));
    return a;
}
__device__ __forceinline__ void cpa16(uint32_t saddr, const void* gptr) {
    asm volatile("cp.async.cg.shared.global [%0], [%1], 16;" :: "r"(saddr), "l"(gptr));
}
__device__ __forceinline__ void ldm_x4(uint32_t* r, uint32_t addr) {
    asm volatile("ldmatrix.sync.aligned.m8n8.x4.shared.b16 {%0,%1,%2,%3}, [%4];"
        : "=r"(r[0]), "=r"(r[1]), "=r"(r[2]), "=r"(r[3]) : "r"(addr));
}
__device__ __forceinline__ void ldm_x2(uint32_t* r, uint32_t addr) {
    asm volatile("ldmatrix.sync.aligned.m8n8.x2.shared.b16 {%0,%1}, [%2];"
        : "=r"(r[0]), "=r"(r[1]) : "r"(addr));
}
__device__ __forceinline__ void mma_bf16(float* c, const uint32_t* a, const uint32_t* b) {
    asm volatile("mma.sync.aligned.m16n8k16.row.col.f32.bf16.bf16.f32 "
        "{%0,%1,%2,%3}, {%4,%5,%6,%7}, {%8,%9}, {%0,%1,%2,%3};"
        : "+f"(c[0]), "+f"(c[1]), "+f"(c[2]), "+f"(c[3])
        : "r"(a[0]), "r"(a[1]), "r"(a[2]), "r"(a[3]), "r"(b[0]), "r"(b[1]));
}

// ---------------- mma.sync bf16x3 GEMM: C[128 x 128] tile, K=384 ----------------
#define BM 128
#define BN 128
#define BK 32
#define KITERS (KTOT/BK)       // 12
#define REGB   10240
#define STAGEB 40960
#define GEMM_SMEM (2*STAGEB)   // 81920

__device__ __forceinline__ void gemm_bf16x3(
    const unsigned short* __restrict__ Ah, const unsigned short* __restrict__ Al,
    const unsigned short* __restrict__ Bh, const unsigned short* __restrict__ Bl,
    float* __restrict__ Y)
{
    extern __shared__ char gsm[];
    const uint32_t smem_base = smem_u32(gsm);
    const int tid = threadIdx.x, wid = tid >> 5, lane = tid & 31;
    const int mBase = (wid >> 2) * 64;       // 2 warp-rows
    const int nBase = (wid & 3) * 32;        // 4 warp-cols

    const int aRow = lane & 15, aCol = lane >> 4;
    const int i16  = lane & 15;
    const int bRow = i16 & 7,  bCol = i16 >> 3;

    float acc[4][4][4];
#pragma unroll
    for (int mt = 0; mt < 4; mt++)
#pragma unroll
        for (int nt = 0; nt < 4; nt++)
#pragma unroll
            for (int q = 0; q < 4; q++) acc[mt][nt][q] = 0.f;

    auto load_stage = [&](int st, int k0) {
        const uint32_t sb = smem_base + (st & 1) * STAGEB;
#pragma unroll
        for (int j = 0; j < 8; j++) {
            const int idx = tid + 256 * j;
            const int region = idx >> 9;
            const int rem = idx & 511;
            const int r = rem >> 2, c = rem & 3;
            const uint32_t saddr = sb + region * REGB + r * 80 + c * 16;
            const unsigned short* gsrc;
            if      (region == 0) gsrc = Ah + (size_t)r * KTOT + k0 + c * 8;
            else if (region == 1) gsrc = Al + (size_t)r * KTOT + k0 + c * 8;
            else if (region == 2) gsrc = Bh + (size_t)r * KTOT + k0 + c * 8;
            else                  gsrc = Bl + (size_t)r * KTOT + k0 + c * 8;
            cpa16(saddr, gsrc);
        }
        asm volatile("cp.async.commit_group;" ::: "memory");
    };

    load_stage(0, 0);

    for (int it = 0; it < KITERS; it++) {
        if (it + 1 < KITERS) {
            load_stage(it + 1, (it + 1) * BK);
            asm volatile("cp.async.wait_group 1;" ::: "memory");
        } else {
            asm volatile("cp.async.wait_group 0;" ::: "memory");
        }
        __syncthreads();

        const uint32_t sb  = smem_base + (it & 1) * STAGEB;
        const uint32_t sAh = sb, sAl = sb + REGB, sBh = sb + 2*REGB, sBl = sb + 3*REGB;

#pragma unroll
        for (int ks = 0; ks < 2; ks++) {
            const uint32_t akb = ks * 32 + aCol * 16;
            const uint32_t bkb = ks * 32 + bCol * 16;
            // B fragments live across the whole ks-step (16 regs)
            uint32_t fBh[4][2], fBl[4][2];
#pragma unroll
            for (int nt = 0; nt < 4; nt++)
                ldm_x2(fBh[nt], sBh + (uint32_t)(nBase + nt*8 + bRow) * 80 + bkb);
#pragma unroll
            for (int nt = 0; nt < 4; nt++)
                ldm_x2(fBl[nt], sBl + (uint32_t)(nBase + nt*8 + bRow) * 80 + bkb);
            // stream A per warp-row tile: only 8 A-regs live at a time
#pragma unroll
            for (int mt = 0; mt < 4; mt++) {
                uint32_t aH[4], aL[4];
                ldm_x4(aH, sAh + (uint32_t)(mBase + mt*16 + aRow) * 80 + akb);
#pragma unroll
                for (int nt = 0; nt < 4; nt++) mma_bf16(acc[mt][nt], aH, fBh[nt]);
#pragma unroll
                for (int nt = 0; nt < 4; nt++) mma_bf16(acc[mt][nt], aH, fBl[nt]);
                ldm_x4(aL, sAl + (uint32_t)(mBase + mt*16 + aRow) * 80 + akb);
#pragma unroll
                for (int nt = 0; nt < 4; nt++) mma_bf16(acc[mt][nt], aL, fBh[nt]);
            }
        }
        __syncthreads();
    }

    const int gr = lane >> 2, gc = (lane & 3) * 2;
#pragma unroll
    for (int mt = 0; mt < 4; mt++) {
#pragma unroll
        for (int nt = 0; nt < 4; nt++) {
            float* d0 = Y + (size_t)(mBase + mt*16 + gr) * HWN + nBase + nt*8 + gc;
            d0[0] = acc[mt][nt][0]; d0[1] = acc[mt][nt][1];
            float* d1 = d0 + 8 * HWN;
            d1[0] = acc[mt][nt][2]; d1[1] = acc[mt][nt][3];
        }
    }
}

__global__ __launch_bounds__(256, 2)
void qkv_gemm_tc()
{
    const int z = blockIdx.z, s = z >> 2, b = z & 3;
    const int row0 = blockIdx.y * BM, n0 = blockIdx.x * BN;
    const size_t aoff = (size_t)(s * CH + row0) * KTOT;
    const int inp = (s == 0) ? 1 : 0;   // q comes from message
    const size_t boff = ((size_t)(inp * BATCH + b) * HWN + n0) * KTOT;
    float* Y = g_pre + ((size_t)z * CH + row0) * HWN + n0;
    gemm_bf16x3(g_wh + aoff, g_wl + aoff, g_inth + boff, g_intl + boff, Y);
}

__global__ __launch_bounds__(256, 2)
void proj_gemm_tc(float* __restrict__ out)
{
    const int b = blockIdx.z;
    const int row0 = blockIdx.y * BM, n0 = blockIdx.x * BN;
    const size_t aoff = (size_t)(1152 + row0) * KTOT;
    const size_t boff = ((size_t)b * HWN + n0) * KTOT;
    float* Y = out + ((size_t)b * CH + row0) * HWN + n0;
    gemm_bf16x3(g_wh + aoff, g_wl + aoff, g_avh + boff, g_avl + boff, Y);
}

// ---------------- convert weights to bf16 hi/lo ----------------
__global__ __launch_bounds__(256) void wconv_kernel(const float* __restrict__ wqkv,
                                                    const float* __restrict__ wproj)
{
    const size_t i = (size_t)blockIdx.x * 256 + threadIdx.x;
    const float f = (i < (size_t)1152 * KTOT) ? wqkv[i] : wproj[i - (size_t)1152 * KTOT];
    const uint32_t bits = __float_as_uint(f);
    const float hi = __uint_as_float(bits & 0xFFFF0000u);
    const __nv_bfloat16 lo = __float2bfloat16(f - hi);
    g_wh[i] = (unsigned short)(bits >> 16);
    g_wl[i] = *(const unsigned short*)&lo;
}

// ---------------- transpose + convert one input ----------------
__global__ __launch_bounds__(256) void trx_kernel(const float* __restrict__ src0, int inp)
{
    __shared__ float t[32][33];
    const int b = blockIdx.z;
    const int p0 = blockIdx.x * 32, c0 = blockIdx.y * 32;
    const int tx = threadIdx.x, ty = threadIdx.y;
    const float* src = src0 + ((size_t)b * CH + c0) * HWN + p0;
    for (int yy = ty; yy < 32; yy += 8) t[yy][tx] = src[(size_t)yy * HWN + tx];
    __syncthreads();
    const int z = inp * BATCH + b;
    unsigned short* dh = g_inth + ((size_t)z * HWN + p0) * CH + c0;
    unsigned short* dl = g_intl + ((size_t)z * HWN + p0) * CH + c0;
    for (int yy = ty; yy < 32; yy += 8) {
        const float f = t[tx][yy];
        const uint32_t bits = __float_as_uint(f);
        const float hi = __uint_as_float(bits & 0xFFFF0000u);
        const __nv_bfloat16 lo = __float2bfloat16(f - hi);
        dh[(size_t)yy * CH + tx] = (unsigned short)(bits >> 16);
        dl[(size_t)yy * CH + tx] = *(const unsigned short*)&lo;
    }
}

// ---------------- depthwise 3x3: 4 px/thread + fused sqnorm partials ----------------
__global__ __launch_bounds__(256)
void dwconv_kernel(const float* __restrict__ wdw)
{
    __shared__ float red[8];

    const int zc = blockIdx.z;
    const int z  = zc / CH;
    const int c  = zc % CH;
    const int s  = z / BATCH;
    const float* wk = wdw + (size_t)(s*CH + c) * 9;
    const float* in   = g_pre  + (size_t)zc * HWN;
    float*       outp = g_post + (size_t)zc * HWN;

    float w[9];
#pragma unroll
    for (int i = 0; i < 9; i++) w[i] = __ldg(&wk[i]);

    const int tx = threadIdx.x;
    const int ty = threadIdx.y;
    const int px0 = tx * 4;
    const int py  = blockIdx.y * 8 + ty;

    float r[3][6];
#pragma unroll
    for (int ky = 0; ky < 3; ky++) {
        const int iy = py + ky - 1;
        if (iy < 0 || iy >= IMG) {
#pragma unroll
            for (int e = 0; e < 6; e++) r[ky][e] = 0.f;
        } else {
            const float* base = in + (size_t)iy * IMG + px0;
            const float4 v = *(const float4*)base;
            r[ky][1] = v.x; r[ky][2] = v.y; r[ky][3] = v.z; r[ky][4] = v.w;
            r[ky][0] = (px0 > 0)       ? __ldg(base - 1) : 0.f;
            r[ky][5] = (px0 + 4 < IMG) ? __ldg(base + 4) : 0.f;
        }
    }

    float a0 = 0.f, a1 = 0.f, a2 = 0.f, a3 = 0.f;
#pragma unroll
    for (int ky = 0; ky < 3; ky++) {
#pragma unroll
        for (int kx = 0; kx < 3; kx++) {
            const float wv = w[ky*3 + kx];
            a0 += r[ky][0 + kx] * wv;
            a1 += r[ky][1 + kx] * wv;
            a2 += r[ky][2 + kx] * wv;
            a3 += r[ky][3 + kx] * wv;
        }
    }
    *(float4*)(outp + (size_t)py * IMG + px0) = make_float4(a0, a1, a2, a3);

    float loc = a0*a0 + a1*a1 + a2*a2 + a3*a3;
    const int tid = ty * 32 + tx;
#pragma unroll
    for (int o = 16; o > 0; o >>= 1) loc += __shfl_xor_sync(0xffffffffu, loc, o);
    if ((tid & 31) == 0) red[tid >> 5] = loc;
    __syncthreads();
    if (tid == 0 && s < 2) {
        float t = 0.f;
#pragma unroll
        for (int i = 0; i < 8; i++) t += red[i];
        g_snp[(size_t)zc * 16 + blockIdx.y] = t;
    }
}

// ---------------- reduce sqnorm partials ----------------
__global__ __launch_bounds__(256)
void sqnorm_kernel()
{
    const int r = blockIdx.x * 256 + threadIdx.x;
    if (r >= 2*BATCH*CH) return;
    float s = 0.f;
#pragma unroll
    for (int i = 0; i < 16; i++) s += g_snp[(size_t)r * 16 + i];
    g_sqn[r] = s;
}

// ---------------- Gram partials: 8x8 threads, 6x6 per thread ----------------
__global__ __launch_bounds__(64)
void gram_kernel()
{
    __shared__ __align__(16) float qs[48][65];
    __shared__ __align__(16) float ks[48][65];

    const int bh = blockIdx.y;
    const int b  = bh >> 3;
    const int h  = bh & 7;
    const int n0 = blockIdx.x * NCHUNK;
    const float* qbase = g_post + ((size_t)(0*BATCH + b)*CH + h*HD) * HWN;
    const float* kbase = g_post + ((size_t)(1*BATCH + b)*CH + h*HD) * HWN;
    const int tid = threadIdx.y * 8 + threadIdx.x;
    const int i0 = threadIdx.y * 6;
    const int j0 = threadIdx.x * 6;

    float acc[6][6];
#pragma unroll
    for (int r = 0; r < 6; r++)
#pragma unroll
        for (int c = 0; c < 6; c++) acc[r][c] = 0.f;

    for (int t = 0; t < NCHUNK; t += 64) {
        for (int e = tid; e < 48*16; e += 64) {
            const int i = e >> 4, j4 = (e & 15) * 4;
            const float4 qv = *(const float4*)&qbase[(size_t)i*HWN + n0 + t + j4];
            const float4 kv = *(const float4*)&kbase[(size_t)i*HWN + n0 + t + j4];
            qs[i][j4+0] = qv.x; qs[i][j4+1] = qv.y; qs[i][j4+2] = qv.z; qs[i][j4+3] = qv.w;
            ks[i][j4+0] = kv.x; ks[i][j4+1] = kv.y; ks[i][j4+2] = kv.z; ks[i][j4+3] = kv.w;
        }
        __syncthreads();
#pragma unroll 4
        for (int nn = 0; nn < 64; nn++) {
            float q[6], k[6];
#pragma unroll
            for (int r = 0; r < 6; r++) q[r] = qs[i0+r][nn];
#pragma unroll
            for (int c = 0; c < 6; c++) k[c] = ks[j0+c][nn];
#pragma unroll
            for (int r = 0; r < 6; r++)
#pragma unroll
                for (int c = 0; c < 6; c++) acc[r][c] += q[r] * k[c];
        }
        __syncthreads();
    }

    float* gp = g_gpart + ((size_t)blockIdx.x * NBH + bh) * (HD*HD);
#pragma unroll
    for (int r = 0; r < 6; r++)
#pragma unroll
        for (int c = 0; c < 6; c++)
            gp[(i0+r)*HD + (j0+c)] = acc[r][c];
}

__global__ __launch_bounds__(1024)
void gram_reduce_kernel()
{
    const int idx = blockIdx.x * 1024 + threadIdx.x;
    float s = 0.f;
#pragma unroll
    for (int ch = 0; ch < GRAM_CHUNKS; ch++)
        s += g_gpart[(size_t)ch * NBH * (HD*HD) + idx];
    g_gram[idx] = s;
}

// ---------------- normalize + temperature + softmax ----------------
__global__ __launch_bounds__(64)
void softmax_kernel(const float* __restrict__ temp)
{
    const int bh = blockIdx.x;
    const int b  = bh >> 3;
    const int h  = bh & 7;
    const int i  = threadIdx.x;
    if (i >= HD) return;

    float* gg = g_gram + (size_t)bh * (HD*HD) + i*HD;
    const float invq = rsqrtf(fmaxf(g_sqn[b*CH + h*HD + i], 1e-24f));
    const float T = temp[h];

    float row[HD];
    float m = -3.4e38f;
#pragma unroll
    for (int j = 0; j < HD; j++) {
        const float invk = rsqrtf(fmaxf(g_sqn[(BATCH + b)*CH + h*HD + j], 1e-24f));
        const float v = gg[j] * invq * invk * T;
        row[j] = v;
        m = fmaxf(m, v);
    }
    float sum = 0.f;
#pragma unroll
    for (int j = 0; j < HD; j++) { row[j] = expf(row[j] - m); sum += row[j]; }
    const float inv = 1.f / sum;
#pragma unroll
    for (int j = 0; j < HD; j++) gg[j] = row[j] * inv;
}

// ---------------- A@V, writing bf16 hi/lo transposed [b][p][c] ----------------
__global__ __launch_bounds__(256)
void av_kernel()
{
    __shared__ __align__(16) float As[HD*HD];
    const int bh = blockIdx.y;
    const int b  = bh >> 3;
    const int h  = bh & 7;
    const int tid = threadIdx.x;
    const int n = blockIdx.x * 256 + tid;

    for (int e = tid; e < HD*HD; e += 256) As[e] = g_gram[(size_t)bh * (HD*HD) + e];
    __syncthreads();

    const float* vbase = g_post + ((size_t)(2*BATCH + b)*CH + h*HD) * HWN + n;
    float acc[HD];
#pragma unroll
    for (int i = 0; i < HD; i++) acc[i] = 0.f;

#pragma unroll 4
    for (int j = 0; j < HD; j++) {
        const float vj = __ldg(&vbase[(size_t)j * HWN]);
#pragma unroll
        for (int i = 0; i < HD; i++) acc[i] += As[i*HD + j] * vj;
    }

    unsigned short* dh = g_avh + ((size_t)b * HWN + n) * CH + h*HD;
    unsigned short* dl = g_avl + ((size_t)b * HWN + n) * CH + h*HD;
#pragma unroll
    for (int i = 0; i < HD; i++) {
        const uint32_t bits = __float_as_uint(acc[i]);
        const float hi = __uint_as_float(bits & 0xFFFF0000u);
        const __nv_bfloat16 lo = __float2bfloat16(acc[i] - hi);
        dh[i] = (unsigned short)(bits >> 16);
        dl[i] = *(const unsigned short*)&lo;
    }
}

// ---------------- launch ----------------
extern "C" void kernel_launch(void* const* d_in, const int* in_sizes, int n_in,
                              void* d_out, int out_size)
{
    const float* x      = (const float*)d_in[0];
    const float* msg    = (const float*)d_in[1];
    const float* w_qkv  = (const float*)d_in[2];
    const float* w_dw   = (const float*)d_in[3];
    const float* w_proj = (const float*)d_in[4];
    const float* temp   = (const float*)d_in[5];
    float* out = (float*)d_out;

    cudaFuncSetAttribute(qkv_gemm_tc, cudaFuncAttributeMaxDynamicSharedMemorySize, GEMM_SMEM);
    cudaFuncSetAttribute(proj_gemm_tc, cudaFuncAttributeMaxDynamicSharedMemorySize, GEMM_SMEM);

    // 0. bf16 hi/lo conversions (trx split so qkv_gemm is launch #4 for ncu)
    wconv_kernel<<<(1536*KTOT)/256, 256>>>(w_qkv, w_proj);
    trx_kernel<<<dim3(HWN/32, CH/32, BATCH), dim3(32,8)>>>(x, 0);
    trx_kernel<<<dim3(HWN/32, CH/32, BATCH), dim3(32,8)>>>(msg, 1);
    // 1. qkv GEMMs on tensor cores (mma.sync bf16x3, 2 CTA/SM)
    qkv_gemm_tc<<<dim3(HWN/BN, CH/BM, 3*BATCH), 256, GEMM_SMEM>>>();
    // 2. depthwise 3x3 (4 px/thread, fused sqnorm partials)
    dwconv_kernel<<<dim3(1, IMG/8, 3*BATCH*CH), dim3(32,8)>>>(w_dw);
    // 3. reduce sqnorm partials
    sqnorm_kernel<<<(2*BATCH*CH + 255)/256, 256>>>();
    // 4-5. Gram (two-phase deterministic, 6x6 register tiles)
    gram_kernel<<<dim3(GRAM_CHUNKS, NBH), dim3(8,8)>>>();
    gram_reduce_kernel<<<(NBH*HD*HD)/1024, 1024>>>();
    // 6. softmax
    softmax_kernel<<<NBH, 64>>>(temp);
    // 7. A@V (emits bf16 hi/lo, transposed)
    av_kernel<<<dim3(HWN/256, NBH), 256>>>();
    // 8. output projection on tensor cores
    proj_gemm_tc<<<dim3(HWN/BN, CH/BM, BATCH), 256, GEMM_SMEM>>>(out);
}

// round 11
// speedup vs baseline: 1.1693x; 1.0098x over previous
#include <cuda_runtime.h>
#include <cuda_bf16.h>
#include <math.h>
#include <stdint.h>

#define BATCH 4
#define CH    384
#define IMG   128
#define HWN   (IMG*IMG)      // 16384
#define NH    8
#define HD    48
#define NBH   (BATCH*NH)     // 32
#define GRAM_CHUNKS 32
#define NCHUNK (HWN/GRAM_CHUNKS)
#define KTOT  384

// ---------------- scratch (device globals; no allocation) ----------------
__device__ __align__(16) float g_pre  [3ull*BATCH*CH*HWN];
__device__ __align__(16) float g_post [3ull*BATCH*CH*HWN];
__device__ __align__(16) float g_snp  [2*BATCH*CH*16];
__device__ __align__(16) float g_sqn  [2*BATCH*CH];
__device__ __align__(16) float g_gpart[(size_t)GRAM_CHUNKS*NBH*HD*HD];
__device__ __align__(16) float g_gram [NBH*HD*HD];
// bf16 split operands
__device__ __align__(16) unsigned short g_wh  [(size_t)1536*KTOT];
__device__ __align__(16) unsigned short g_wl  [(size_t)1536*KTOT];
__device__ __align__(16) unsigned short g_inth[(size_t)2*BATCH*HWN*CH];  // [inp][b][p][c]
__device__ __align__(16) unsigned short g_intl[(size_t)2*BATCH*HWN*CH];
__device__ __align__(16) unsigned short g_avh [(size_t)BATCH*HWN*CH];    // [b][p][c]
__device__ __align__(16) unsigned short g_avl [(size_t)BATCH*HWN*CH];

// ---------------- PTX helpers (sm_80-level only) ----------------
__device__ __forceinline__ uint32_t smem_u32(const void* p) {
    uint32_t a;
    asm("{ .reg .u64 t; cvta.to.shared.u64 t, %1; cvt.u32.u64 %0, t; }" : "=r"(a) : "l"(p));
    return a;
}
__device__ __forceinline__ void cpa16(uint32_t saddr, const void* gptr) {
    asm volatile("cp.async.cg.shared.global [%0], [%1], 16;" :: "r"(saddr), "l"(gptr));
}
__device__ __forceinline__ void ldm_x4(uint32_t* r, uint32_t addr) {
    asm volatile("ldmatrix.sync.aligned.m8n8.x4.shared.b16 {%0,%1,%2,%3}, [%4];"
        : "=r"(r[0]), "=r"(r[1]), "=r"(r[2]), "=r"(r[3]) : "r"(addr));
}
__device__ __forceinline__ void ldm_x2(uint32_t* r, uint32_t addr) {
    asm volatile("ldmatrix.sync.aligned.m8n8.x2.shared.b16 {%0,%1}, [%2];"
        : "=r"(r[0]), "=r"(r[1]) : "r"(addr));
}
__device__ __forceinline__ void mma_bf16(float* c, const uint32_t* a, const uint32_t* b) {
    asm volatile("mma.sync.aligned.m16n8k16.row.col.f32.bf16.bf16.f32 "
        "{%0,%1,%2,%3}, {%4,%5,%6,%7}, {%8,%9}, {%0,%1,%2,%3};"
        : "+f"(c[0]), "+f"(c[1]), "+f"(c[2]), "+f"(c[3])
        : "r"(a[0]), "r"(a[1]), "r"(a[2]), "r"(a[3]), "r"(b[0]), "r"(b[1]));
}

// ---------------- mma.sync bf16x3 GEMM: C[128 x 128] tile, K=384 ----------------
#define BM 128
#define BN 128
#define BK 32
#define KITERS (KTOT/BK)       // 12
#define REGB   10240
#define STAGEB 40960
#define GEMM_SMEM (2*STAGEB)   // 81920

__device__ __forceinline__ void gemm_bf16x3(
    const unsigned short* __restrict__ Ah, const unsigned short* __restrict__ Al,
    const unsigned short* __restrict__ Bh, const unsigned short* __restrict__ Bl,
    float* __restrict__ Y)
{
    extern __shared__ char gsm[];
    const uint32_t smem_base = smem_u32(gsm);
    const int tid = threadIdx.x, wid = tid >> 5, lane = tid & 31;
    const int mBase = (wid >> 2) * 64;       // 2 warp-rows
    const int nBase = (wid & 3) * 32;        // 4 warp-cols

    const int aRow = lane & 15, aCol = lane >> 4;
    const int i16  = lane & 15;
    const int bRow = i16 & 7,  bCol = i16 >> 3;

    float acc[4][4][4];
#pragma unroll
    for (int mt = 0; mt < 4; mt++)
#pragma unroll
        for (int nt = 0; nt < 4; nt++)
#pragma unroll
            for (int q = 0; q < 4; q++) acc[mt][nt][q] = 0.f;

    auto load_stage = [&](int st, int k0) {
        const uint32_t sb = smem_base + (st & 1) * STAGEB;
#pragma unroll
        for (int j = 0; j < 8; j++) {
            const int idx = tid + 256 * j;
            const int region = idx >> 9;
            const int rem = idx & 511;
            const int r = rem >> 2, c = rem & 3;
            const uint32_t saddr = sb + region * REGB + r * 80 + c * 16;
            const unsigned short* gsrc;
            if      (region == 0) gsrc = Ah + (size_t)r * KTOT + k0 + c * 8;
            else if (region == 1) gsrc = Al + (size_t)r * KTOT + k0 + c * 8;
            else if (region == 2) gsrc = Bh + (size_t)r * KTOT + k0 + c * 8;
            else                  gsrc = Bl + (size_t)r * KTOT + k0 + c * 8;
            cpa16(saddr, gsrc);
        }
        asm volatile("cp.async.commit_group;" ::: "memory");
    };

    load_stage(0, 0);

    for (int it = 0; it < KITERS; it++) {
        if (it + 1 < KITERS) {
            load_stage(it + 1, (it + 1) * BK);
            asm volatile("cp.async.wait_group 1;" ::: "memory");
        } else {
            asm volatile("cp.async.wait_group 0;" ::: "memory");
        }
        __syncthreads();

        const uint32_t sb  = smem_base + (it & 1) * STAGEB;
        const uint32_t sAh = sb, sAl = sb + REGB, sBh = sb + 2*REGB, sBl = sb + 3*REGB;

#pragma unroll
        for (int ks = 0; ks < 2; ks++) {
            const uint32_t akb = ks * 32 + aCol * 16;
            const uint32_t bkb = ks * 32 + bCol * 16;
            uint32_t fBh[4][2], fBl[4][2];
#pragma unroll
            for (int nt = 0; nt < 4; nt++)
                ldm_x2(fBh[nt], sBh + (uint32_t)(nBase + nt*8 + bRow) * 80 + bkb);
#pragma unroll
            for (int nt = 0; nt < 4; nt++)
                ldm_x2(fBl[nt], sBl + (uint32_t)(nBase + nt*8 + bRow) * 80 + bkb);
#pragma unroll
            for (int mt = 0; mt < 4; mt++) {
                uint32_t aH[4], aL[4];
                ldm_x4(aH, sAh + (uint32_t)(mBase + mt*16 + aRow) * 80 + akb);
#pragma unroll
                for (int nt = 0; nt < 4; nt++) mma_bf16(acc[mt][nt], aH, fBh[nt]);
#pragma unroll
                for (int nt = 0; nt < 4; nt++) mma_bf16(acc[mt][nt], aH, fBl[nt]);
                ldm_x4(aL, sAl + (uint32_t)(mBase + mt*16 + aRow) * 80 + akb);
#pragma unroll
                for (int nt = 0; nt < 4; nt++) mma_bf16(acc[mt][nt], aL, fBh[nt]);
            }
        }
        __syncthreads();
    }

    const int gr = lane >> 2, gc = (lane & 3) * 2;
#pragma unroll
    for (int mt = 0; mt < 4; mt++) {
#pragma unroll
        for (int nt = 0; nt < 4; nt++) {
            float* d0 = Y + (size_t)(mBase + mt*16 + gr) * HWN + nBase + nt*8 + gc;
            d0[0] = acc[mt][nt][0]; d0[1] = acc[mt][nt][1];
            float* d1 = d0 + 8 * HWN;
            d1[0] = acc[mt][nt][2]; d1[1] = acc[mt][nt][3];
        }
    }
}

__global__ __launch_bounds__(256, 2)
void qkv_gemm_tc()
{
    const int z = blockIdx.z, s = z >> 2, b = z & 3;
    const int row0 = blockIdx.y * BM, n0 = blockIdx.x * BN;
    const size_t aoff = (size_t)(s * CH + row0) * KTOT;
    const int inp = (s == 0) ? 1 : 0;   // q comes from message
    const size_t boff = ((size_t)(inp * BATCH + b) * HWN + n0) * KTOT;
    float* Y = g_pre + ((size_t)z * CH + row0) * HWN + n0;
    gemm_bf16x3(g_wh + aoff, g_wl + aoff, g_inth + boff, g_intl + boff, Y);
}

__global__ __launch_bounds__(256, 2)
void proj_gemm_tc(float* __restrict__ out)
{
    const int b = blockIdx.z;
    const int row0 = blockIdx.y * BM, n0 = blockIdx.x * BN;
    const size_t aoff = (size_t)(1152 + row0) * KTOT;
    const size_t boff = ((size_t)b * HWN + n0) * KTOT;
    float* Y = out + ((size_t)b * CH + row0) * HWN + n0;
    gemm_bf16x3(g_wh + aoff, g_wl + aoff, g_avh + boff, g_avl + boff, Y);
}

// ---------------- convert weights to bf16 hi/lo ----------------
__global__ __launch_bounds__(256) void wconv_kernel(const float* __restrict__ wqkv,
                                                    const float* __restrict__ wproj)
{
    const size_t i = (size_t)blockIdx.x * 256 + threadIdx.x;
    const float f = (i < (size_t)1152 * KTOT) ? wqkv[i] : wproj[i - (size_t)1152 * KTOT];
    const uint32_t bits = __float_as_uint(f);
    const float hi = __uint_as_float(bits & 0xFFFF0000u);
    const __nv_bfloat16 lo = __float2bfloat16(f - hi);
    g_wh[i] = (unsigned short)(bits >> 16);
    g_wl[i] = *(const unsigned short*)&lo;
}

// ---------------- transpose + convert one input ----------------
__global__ __launch_bounds__(256) void trx_kernel(const float* __restrict__ src0, int inp)
{
    __shared__ float t[32][33];
    const int b = blockIdx.z;
    const int p0 = blockIdx.x * 32, c0 = blockIdx.y * 32;
    const int tx = threadIdx.x, ty = threadIdx.y;
    const float* src = src0 + ((size_t)b * CH + c0) * HWN + p0;
    for (int yy = ty; yy < 32; yy += 8) t[yy][tx] = src[(size_t)yy * HWN + tx];
    __syncthreads();
    const int z = inp * BATCH + b;
    unsigned short* dh = g_inth + ((size_t)z * HWN + p0) * CH + c0;
    unsigned short* dl = g_intl + ((size_t)z * HWN + p0) * CH + c0;
    for (int yy = ty; yy < 32; yy += 8) {
        const float f = t[tx][yy];
        const uint32_t bits = __float_as_uint(f);
        const float hi = __uint_as_float(bits & 0xFFFF0000u);
        const __nv_bfloat16 lo = __float2bfloat16(f - hi);
        dh[(size_t)yy * CH + tx] = (unsigned short)(bits >> 16);
        dl[(size_t)yy * CH + tx] = *(const unsigned short*)&lo;
    }
}

// ---------------- depthwise 3x3: warp-per-row, shfl horizontal neighbors ----------------
__global__ __launch_bounds__(256)
void dwconv_kernel(const float* __restrict__ wdw)
{
    __shared__ float red[8];

    const int zc = blockIdx.z;
    const int z  = zc / CH;
    const int c  = zc % CH;
    const int s  = z / BATCH;
    const float* wk = wdw + (size_t)(s*CH + c) * 9;
    const float* in   = g_pre  + (size_t)zc * HWN;
    float*       outp = g_post + (size_t)zc * HWN;

    float w[9];
#pragma unroll
    for (int i = 0; i < 9; i++) w[i] = __ldg(&wk[i]);

    const int lane = threadIdx.x;          // 0..31  (warp = one image row)
    const int wy   = threadIdx.y;          // 0..7
    const int px0 = lane * 4;
    const int py  = blockIdx.y * 8 + wy;

    float r[3][6];
#pragma unroll
    for (int ky = 0; ky < 3; ky++) {
        const int iy = py + ky - 1;        // warp-uniform condition
        if (iy < 0 || iy >= IMG) {
#pragma unroll
            for (int e = 0; e < 6; e++) r[ky][e] = 0.f;
        } else {
            const float4 v = *(const float4*)(in + (size_t)iy * IMG + px0);
            float left  = __shfl_up_sync(0xffffffffu, v.w, 1);
            float right = __shfl_down_sync(0xffffffffu, v.x, 1);
            if (lane == 0)  left  = 0.f;
            if (lane == 31) right = 0.f;
            r[ky][0] = left;  r[ky][1] = v.x; r[ky][2] = v.y;
            r[ky][3] = v.z;   r[ky][4] = v.w; r[ky][5] = right;
        }
    }

    float a0 = 0.f, a1 = 0.f, a2 = 0.f, a3 = 0.f;
#pragma unroll
    for (int ky = 0; ky < 3; ky++) {
#pragma unroll
        for (int kx = 0; kx < 3; kx++) {
            const float wv = w[ky*3 + kx];
            a0 += r[ky][0 + kx] * wv;
            a1 += r[ky][1 + kx] * wv;
            a2 += r[ky][2 + kx] * wv;
            a3 += r[ky][3 + kx] * wv;
        }
    }
    *(float4*)(outp + (size_t)py * IMG + px0) = make_float4(a0, a1, a2, a3);

    float loc = a0*a0 + a1*a1 + a2*a2 + a3*a3;
    const int tid = wy * 32 + lane;
#pragma unroll
    for (int o = 16; o > 0; o >>= 1) loc += __shfl_xor_sync(0xffffffffu, loc, o);
    if ((tid & 31) == 0) red[tid >> 5] = loc;
    __syncthreads();
    if (tid == 0 && s < 2) {
        float t = 0.f;
#pragma unroll
        for (int i = 0; i < 8; i++) t += red[i];
        g_snp[(size_t)zc * 16 + blockIdx.y] = t;
    }
}

// ---------------- reduce sqnorm partials ----------------
__global__ __launch_bounds__(256)
void sqnorm_kernel()
{
    const int r = blockIdx.x * 256 + threadIdx.x;
    if (r >= 2*BATCH*CH) return;
    float s = 0.f;
#pragma unroll
    for (int i = 0; i < 16; i++) s += g_snp[(size_t)r * 16 + i];
    g_sqn[r] = s;
}

// ---------------- Gram partials: 8x8 threads, 6x6 per thread ----------------
__global__ __launch_bounds__(64)
void gram_kernel()
{
    __shared__ __align__(16) float qs[48][65];
    __shared__ __align__(16) float ks[48][65];

    const int bh = blockIdx.y;
    const int b  = bh >> 3;
    const int h  = bh & 7;
    const int n0 = blockIdx.x * NCHUNK;
    const float* qbase = g_post + ((size_t)(0*BATCH + b)*CH + h*HD) * HWN;
    const float* kbase = g_post + ((size_t)(1*BATCH + b)*CH + h*HD) * HWN;
    const int tid = threadIdx.y * 8 + threadIdx.x;
    const int i0 = threadIdx.y * 6;
    const int j0 = threadIdx.x * 6;

    float acc[6][6];
#pragma unroll
    for (int r = 0; r < 6; r++)
#pragma unroll
        for (int c = 0; c < 6; c++) acc[r][c] = 0.f;

    for (int t = 0; t < NCHUNK; t += 64) {
        for (int e = tid; e < 48*16; e += 64) {
            const int i = e >> 4, j4 = (e & 15) * 4;
            const float4 qv = *(const float4*)&qbase[(size_t)i*HWN + n0 + t + j4];
            const float4 kv = *(const float4*)&kbase[(size_t)i*HWN + n0 + t + j4];
            qs[i][j4+0] = qv.x; qs[i][j4+1] = qv.y; qs[i][j4+2] = qv.z; qs[i][j4+3] = qv.w;
            ks[i][j4+0] = kv.x; ks[i][j4+1] = kv.y; ks[i][j4+2] = kv.z; ks[i][j4+3] = kv.w;
        }
        __syncthreads();
#pragma unroll 4
        for (int nn = 0; nn < 64; nn++) {
            float q[6], k[6];
#pragma unroll
            for (int r = 0; r < 6; r++) q[r] = qs[i0+r][nn];
#pragma unroll
            for (int c = 0; c < 6; c++) k[c] = ks[j0+c][nn];
#pragma unroll
            for (int r = 0; r < 6; r++)
#pragma unroll
                for (int c = 0; c < 6; c++) acc[r][c] += q[r] * k[c];
        }
        __syncthreads();
    }

    float* gp = g_gpart + ((size_t)blockIdx.x * NBH + bh) * (HD*HD);
#pragma unroll
    for (int r = 0; r < 6; r++)
#pragma unroll
        for (int c = 0; c < 6; c++)
            gp[(i0+r)*HD + (j0+c)] = acc[r][c];
}

__global__ __launch_bounds__(1024)
void gram_reduce_kernel()
{
    const int idx = blockIdx.x * 1024 + threadIdx.x;
    float s = 0.f;
#pragma unroll
    for (int ch = 0; ch < GRAM_CHUNKS; ch++)
        s += g_gpart[(size_t)ch * NBH * (HD*HD) + idx];
    g_gram[idx] = s;
}

// ---------------- normalize + temperature + softmax ----------------
__global__ __launch_bounds__(64)
void softmax_kernel(const float* __restrict__ temp)
{
    const int bh = blockIdx.x;
    const int b  = bh >> 3;
    const int h  = bh & 7;
    const int i  = threadIdx.x;
    if (i >= HD) return;

    float* gg = g_gram + (size_t)bh * (HD*HD) + i*HD;
    const float invq = rsqrtf(fmaxf(g_sqn[b*CH + h*HD + i], 1e-24f));
    const float T = temp[h];

    float row[HD];
    float m = -3.4e38f;
#pragma unroll
    for (int j = 0; j < HD; j++) {
        const float invk = rsqrtf(fmaxf(g_sqn[(BATCH + b)*CH + h*HD + j], 1e-24f));
        const float v = gg[j] * invq * invk * T;
        row[j] = v;
        m = fmaxf(m, v);
    }
    float sum = 0.f;
#pragma unroll
    for (int j = 0; j < HD; j++) { row[j] = expf(row[j] - m); sum += row[j]; }
    const float inv = 1.f / sum;
#pragma unroll
    for (int j = 0; j < HD; j++) gg[j] = row[j] * inv;
}

// ---------------- A@V with smem-staged coalesced bf16 hi/lo stores ----------------
#define AVPAD 49
#define AV_SMEM ((HD*HD + 256*AVPAD) * 4)   // 9216 + 50176 = 59392 B

__global__ __launch_bounds__(256)
void av_kernel()
{
    extern __shared__ float avdyn[];
    float* As   = avdyn;                  // [HD*HD]
    float* sacc = avdyn + HD*HD;          // [256][AVPAD]

    const int bh = blockIdx.y;
    const int b  = bh >> 3;
    const int h  = bh & 7;
    const int tid = threadIdx.x;
    const int n0 = blockIdx.x * 256;
    const int n = n0 + tid;

    for (int e = tid; e < HD*HD; e += 256) As[e] = g_gram[(size_t)bh * (HD*HD) + e];
    __syncthreads();

    const float* vbase = g_post + ((size_t)(2*BATCH + b)*CH + h*HD) * HWN + n;
    float acc[HD];
#pragma unroll
    for (int i = 0; i < HD; i++) acc[i] = 0.f;

#pragma unroll 4
    for (int j = 0; j < HD; j++) {
        const float vj = __ldg(&vbase[(size_t)j * HWN]);
#pragma unroll
        for (int i = 0; i < HD; i++) acc[i] += As[i*HD + j] * vj;
    }

    // stage into smem (pad 49 -> conflict-free), then coalesced packed stores
#pragma unroll
    for (int i = 0; i < HD; i++) sacc[tid * AVPAD + i] = acc[i];
    __syncthreads();

    unsigned short* dhb = g_avh + ((size_t)b * HWN + n0) * CH + h*HD;
    unsigned short* dlb = g_avl + ((size_t)b * HWN + n0) * CH + h*HD;
#pragma unroll
    for (int k = 0; k < 24; k++) {
        const int wv = tid + k * 256;          // 0 .. 6143
        const int p  = wv / 24;
        const int cw = wv % 24;
        const float f0 = sacc[p * AVPAD + 2*cw];
        const float f1 = sacc[p * AVPAD + 2*cw + 1];
        const uint32_t b0 = __float_as_uint(f0);
        const uint32_t b1 = __float_as_uint(f1);
        const uint32_t hiw = (b0 >> 16) | (b1 & 0xFFFF0000u);
        *(uint32_t*)(dhb + (size_t)p * CH + 2*cw) = hiw;
        const float h0 = __uint_as_float(b0 & 0xFFFF0000u);
        const float h1 = __uint_as_float(b1 & 0xFFFF0000u);
        const __nv_bfloat16 l0 = __float2bfloat16(f0 - h0);
        const __nv_bfloat16 l1 = __float2bfloat16(f1 - h1);
        const uint32_t low = (uint32_t)(*(const unsigned short*)&l0)
                           | ((uint32_t)(*(const unsigned short*)&l1) << 16);
        *(uint32_t*)(dlb + (size_t)p * CH + 2*cw) = low;
    }
}

// ---------------- launch ----------------
extern "C" void kernel_launch(void* const* d_in, const int* in_sizes, int n_in,
                              void* d_out, int out_size)
{
    const float* x      = (const float*)d_in[0];
    const float* msg    = (const float*)d_in[1];
    const float* w_qkv  = (const float*)d_in[2];
    const float* w_dw   = (const float*)d_in[3];
    const float* w_proj = (const float*)d_in[4];
    const float* temp   = (const float*)d_in[5];
    float* out = (float*)d_out;

    cudaFuncSetAttribute(qkv_gemm_tc, cudaFuncAttributeMaxDynamicSharedMemorySize, GEMM_SMEM);
    cudaFuncSetAttribute(proj_gemm_tc, cudaFuncAttributeMaxDynamicSharedMemorySize, GEMM_SMEM);
    cudaFuncSetAttribute(av_kernel,   cudaFuncAttributeMaxDynamicSharedMemorySize, AV_SMEM);

    // 0. bf16 hi/lo conversions (trx split so qkv_gemm is launch #4 for ncu)
    wconv_kernel<<<(1536*KTOT)/256, 256>>>(w_qkv, w_proj);
    trx_kernel<<<dim3(HWN/32, CH/32, BATCH), dim3(32,8)>>>(x, 0);
    trx_kernel<<<dim3(HWN/32, CH/32, BATCH), dim3(32,8)>>>(msg, 1);
    // 1. qkv GEMMs on tensor cores (mma.sync bf16x3, 2 CTA/SM)
    qkv_gemm_tc<<<dim3(HWN/BN, CH/BM, 3*BATCH), 256, GEMM_SMEM>>>();
    // 2. depthwise 3x3 (warp-per-row + shfl, fused sqnorm partials)
    dwconv_kernel<<<dim3(1, IMG/8, 3*BATCH*CH), dim3(32,8)>>>(w_dw);
    // 3. reduce sqnorm partials
    sqnorm_kernel<<<(2*BATCH*CH + 255)/256, 256>>>();
    // 4-5. Gram (two-phase deterministic, 6x6 register tiles)
    gram_kernel<<<dim3(GRAM_CHUNKS, NBH), dim3(8,8)>>>();
    gram_reduce_kernel<<<(NBH*HD*HD)/1024, 1024>>>();
    // 6. softmax
    softmax_kernel<<<NBH, 64>>>(temp);
    // 7. A@V (smem-staged coalesced bf16 hi/lo stores)
    av_kernel<<<dim3(HWN/256, NBH), 256, AV_SMEM>>>();
    // 8. output projection on tensor cores
    proj_gemm_tc<<<dim3(HWN/BN, CH/BM, BATCH), 256, GEMM_SMEM>>>(out);
}